// round 3
// baseline (speedup 1.0000x reference)
#include <cuda_runtime.h>
#include <cuda_bf16.h>

#define BB 8
#define FF 16384
#define HH 256
#define NROWS (BB*FF)
#define CH (FF/1024)   // 16 elements per thread in scan kernel

// Scratch (allocation-free rule: __device__ globals)
__device__ float g_d[NROWS*4];     // per-step delta quaternions exp(w*dt)
__device__ float g_cacc[NROWS*3];  // corrected acc
__device__ float g_a[NROWS*3];     // world-frame accel (+gravity)

// quaternion stored as float4: .x=w, .y=v1, .z=v2, .w=v3
__device__ __forceinline__ float4 qmul(float4 q, float4 p) {
    float4 r;
    r.x = q.x*p.x - q.y*p.y - q.z*p.z - q.w*p.w;
    r.y = q.x*p.y + p.x*q.y + (q.z*p.w - q.w*p.z);
    r.z = q.x*p.z + p.x*q.z + (q.w*p.y - q.y*p.w);
    r.w = q.x*p.w + p.x*q.w + (q.y*p.z - q.z*p.y);
    return r;
}

// ---------------------------------------------------------------------------
// Kernel 1: MLP correction + delta-quaternion precompute (fully parallel)
// ---------------------------------------------------------------------------
__global__ void __launch_bounds__(256)
mlp_kernel(const float* __restrict__ acc, const float* __restrict__ gyro,
           const float* __restrict__ dt,
           const float* __restrict__ W_enc, const float* __restrict__ b_enc,
           const float* __restrict__ W_dec, const float* __restrict__ b_dec,
           float* __restrict__ out)
{
    // sw[h*12 + 0..5] = W_enc[:,h], sw[h*12 + 6..11] = W_dec[h,:]
    __shared__ __align__(16) float sw[HH*12];
    __shared__ float sb[HH];
    __shared__ float sbd[8];
    int tid = threadIdx.x;
    for (int i = tid; i < HH; i += blockDim.x) {
        #pragma unroll
        for (int k = 0; k < 6; k++) sw[i*12 + k] = W_enc[k*HH + i];
        #pragma unroll
        for (int k = 0; k < 6; k++) sw[i*12 + 6 + k] = W_dec[i*6 + k];
        sb[i] = b_enc[i];
    }
    if (tid < 6) sbd[tid] = b_dec[tid];
    __syncthreads();

    int r = blockIdx.x * blockDim.x + tid;   // grid sized exactly NROWS
    float x0 = acc[r*3+0], x1 = acc[r*3+1], x2 = acc[r*3+2];
    float x3 = gyro[r*3+0], x4 = gyro[r*3+1], x5 = gyro[r*3+2];

    float c0=0.f,c1=0.f,c2=0.f,c3=0.f,c4=0.f,c5=0.f;
    #pragma unroll 4
    for (int h = 0; h < HH; h++) {
        const float4* p = reinterpret_cast<const float4*>(sw + h*12);
        float4 wa = p[0], wb = p[1], wc = p[2];
        float pre = sb[h];
        pre = fmaf(wa.x, x0, pre); pre = fmaf(wa.y, x1, pre);
        pre = fmaf(wa.z, x2, pre); pre = fmaf(wa.w, x3, pre);
        pre = fmaf(wb.x, x4, pre); pre = fmaf(wb.y, x5, pre);
        // gelu (tanh approximation, matching jax.nn.gelu default)
        float u  = 0.7978845608028654f * fmaf(0.044715f*pre, pre*pre, pre);
        float e  = __expf(2.0f*u);
        float th = 1.0f - 2.0f/(e + 1.0f);       // robust: saturates to +/-1
        float feat = 0.5f * pre * (1.0f + th);
        c0 = fmaf(feat, wb.z, c0);
        c1 = fmaf(feat, wb.w, c1);
        c2 = fmaf(feat, wc.x, c2);
        c3 = fmaf(feat, wc.y, c3);
        c4 = fmaf(feat, wc.z, c4);
        c5 = fmaf(feat, wc.w, c5);
    }
    c0 += sbd[0]; c1 += sbd[1]; c2 += sbd[2];
    c3 += sbd[3]; c4 += sbd[4]; c5 += sbd[5];

    size_t ob = (size_t)r * 16;
    out[ob+10] = c0; out[ob+11] = c1; out[ob+12] = c2;
    out[ob+13] = c3; out[ob+14] = c4; out[ob+15] = c5;

    // corrected acc -> scratch
    g_cacc[r*3+0] = c0 + x0;
    g_cacc[r*3+1] = c1 + x1;
    g_cacc[r*3+2] = c2 + x2;

    // delta quaternion: quat_exp(corrected_gyro * dt)
    float dtv = dt[r];
    float v0 = (c3 + x3) * dtv;
    float v1 = (c4 + x4) * dtv;
    float v2 = (c5 + x5) * dtv;
    float t2 = v0*v0 + v1*v1 + v2*v2;
    float theta = sqrtf(t2 + 1e-16f);
    float half  = 0.5f * theta;
    float w  = cosf(half);
    float sc = (t2 < 1e-12f) ? (0.5f - t2 * (1.0f/48.0f)) : (sinf(half) / theta);
    reinterpret_cast<float4*>(g_d)[r] = make_float4(w, v0*sc, v1*sc, v2*sc);
}

// ---------------------------------------------------------------------------
// Kernel 2: per-batch parallel scans (quat prefix product + affine pos/vel)
// ---------------------------------------------------------------------------
__global__ void __launch_bounds__(1024)
scan_kernel(const float* __restrict__ dt,
            const float* __restrict__ init_pos, const float* __restrict__ init_vel,
            const float* __restrict__ init_rot, float* __restrict__ out)
{
    __shared__ __align__(16) float smem[1024*7];
    int b = blockIdx.x, t = threadIdx.x;
    int base = b*FF + t*CH;
    const float4* gd4 = reinterpret_cast<const float4*>(g_d);

    // ---- Pass A: chunk-local quat product, then block inclusive scan ----
    float4 L = gd4[base];
    #pragma unroll
    for (int j = 1; j < CH; j++) L = qmul(L, gd4[base + j]);

    float4* sq = reinterpret_cast<float4*>(smem);
    sq[t] = L;
    __syncthreads();
    for (int off = 1; off < 1024; off <<= 1) {
        float4 v = sq[t];
        if (t >= off) v = qmul(sq[t - off], v);
        __syncthreads();
        sq[t] = v;
        __syncthreads();
    }
    float4 q0 = make_float4(init_rot[b*4+0], init_rot[b*4+1],
                            init_rot[b*4+2], init_rot[b*4+3]);
    float4 E = (t == 0) ? q0 : qmul(q0, sq[t-1]);
    __syncthreads();  // all reads of sq done before smem reuse

    // ---- Pass B: world accel, rot output, chunk (T,S,C) summary ----
    float T = 0.f;
    float S0=0.f,S1=0.f,S2=0.f;   // chunk-local velocity accumulation
    float C0=0.f,C1=0.f,C2=0.f;   // chunk-local position increment (vel_in=0)
    #pragma unroll 4
    for (int j = 0; j < CH; j++) {
        int idx = base + j;
        float rn = rsqrtf(E.x*E.x + E.y*E.y + E.z*E.z + E.w*E.w);
        float qw = E.x*rn, q1 = E.y*rn, q2 = E.z*rn, q3 = E.w*rn;
        float v1 = g_cacc[idx*3+0], v2 = g_cacc[idx*3+1], v3 = g_cacc[idx*3+2];
        // quat_rotate(q, v): tt = cross(qv,v)+qw*v; r = v + 2*cross(qv,tt)
        float t1 = (q2*v3 - q3*v2) + qw*v1;
        float t2_ = (q3*v1 - q1*v3) + qw*v2;
        float t3 = (q1*v2 - q2*v1) + qw*v3;
        float a0 = v1 + 2.0f*(q2*t3 - q3*t2_);
        float a1 = v2 + 2.0f*(q3*t1 - q1*t3);
        float a2 = v3 + 2.0f*(q1*t2_ - q2*t1) - 9.81007f;
        g_a[idx*3+0] = a0; g_a[idx*3+1] = a1; g_a[idx*3+2] = a2;

        float dtv = dt[idx];
        float hd = 0.5f*dtv*dtv;
        C0 += S0*dtv + a0*hd;
        C1 += S1*dtv + a1*hd;
        C2 += S2*dtv + a2*hd;
        S0 += a0*dtv; S1 += a1*dtv; S2 += a2*dtv;
        T  += dtv;

        // advance quaternion and emit normalized rot
        E = qmul(E, gd4[idx]);
        float rn2 = rsqrtf(E.x*E.x + E.y*E.y + E.z*E.z + E.w*E.w);
        size_t ob = (size_t)idx * 16;
        out[ob+6] = E.x*rn2; out[ob+7] = E.y*rn2;
        out[ob+8] = E.z*rn2; out[ob+9] = E.w*rn2;
    }

    // ---- (T,S,C) block inclusive scan: C = Cl + Cr + Sl*Tr ----
    smem[t*7+0] = T;
    smem[t*7+1] = S0; smem[t*7+2] = S1; smem[t*7+3] = S2;
    smem[t*7+4] = C0; smem[t*7+5] = C1; smem[t*7+6] = C2;
    __syncthreads();
    for (int off = 1; off < 1024; off <<= 1) {
        float rT = smem[t*7+0];
        float rS0 = smem[t*7+1], rS1 = smem[t*7+2], rS2 = smem[t*7+3];
        float rC0 = smem[t*7+4], rC1 = smem[t*7+5], rC2 = smem[t*7+6];
        if (t >= off) {
            int l = (t - off)*7;
            float lT = smem[l+0];
            float lS0 = smem[l+1], lS1 = smem[l+2], lS2 = smem[l+3];
            float lC0 = smem[l+4], lC1 = smem[l+5], lC2 = smem[l+6];
            rC0 = lC0 + rC0 + lS0*rT;
            rC1 = lC1 + rC1 + lS1*rT;
            rC2 = lC2 + rC2 + lS2*rT;
            rS0 += lS0; rS1 += lS1; rS2 += lS2;
            rT += lT;
        }
        __syncthreads();
        smem[t*7+0] = rT;
        smem[t*7+1] = rS0; smem[t*7+2] = rS1; smem[t*7+3] = rS2;
        smem[t*7+4] = rC0; smem[t*7+5] = rC1; smem[t*7+6] = rC2;
        __syncthreads();
    }

    float Te=0.f, Se0=0.f,Se1=0.f,Se2=0.f, Ce0=0.f,Ce1=0.f,Ce2=0.f;
    if (t > 0) {
        int l = (t-1)*7;
        Te = smem[l+0];
        Se0 = smem[l+1]; Se1 = smem[l+2]; Se2 = smem[l+3];
        Ce0 = smem[l+4]; Ce1 = smem[l+5]; Ce2 = smem[l+6];
    }
    float iv0 = init_vel[b*3+0], iv1 = init_vel[b*3+1], iv2 = init_vel[b*3+2];
    float p0 = init_pos[b*3+0] + iv0*Te + Ce0;
    float p1 = init_pos[b*3+1] + iv1*Te + Ce1;
    float p2 = init_pos[b*3+2] + iv2*Te + Ce2;
    float ve0 = iv0 + Se0, ve1 = iv1 + Se1, ve2 = iv2 + Se2;

    // ---- Pass C: final per-step pos/vel ----
    #pragma unroll 4
    for (int j = 0; j < CH; j++) {
        int idx = base + j;
        float a0 = g_a[idx*3+0], a1 = g_a[idx*3+1], a2 = g_a[idx*3+2];
        float dtv = dt[idx];
        float hd = 0.5f*dtv*dtv;
        p0 += ve0*dtv + a0*hd;
        p1 += ve1*dtv + a1*hd;
        p2 += ve2*dtv + a2*hd;
        ve0 += a0*dtv; ve1 += a1*dtv; ve2 += a2*dtv;
        size_t ob = (size_t)idx * 16;
        out[ob+0] = p0;  out[ob+1] = p1;  out[ob+2] = p2;
        out[ob+3] = ve0; out[ob+4] = ve1; out[ob+5] = ve2;
    }
}

// ---------------------------------------------------------------------------
extern "C" void kernel_launch(void* const* d_in, const int* in_sizes, int n_in,
                              void* d_out, int out_size)
{
    const float* acc      = (const float*)d_in[0];
    const float* gyro     = (const float*)d_in[1];
    const float* dt       = (const float*)d_in[2];
    const float* init_pos = (const float*)d_in[3];
    const float* init_vel = (const float*)d_in[4];
    const float* init_rot = (const float*)d_in[5];
    const float* W_enc    = (const float*)d_in[6];
    const float* b_enc    = (const float*)d_in[7];
    const float* W_dec    = (const float*)d_in[8];
    const float* b_dec    = (const float*)d_in[9];
    float* out = (float*)d_out;

    mlp_kernel<<<NROWS/256, 256>>>(acc, gyro, dt, W_enc, b_enc, W_dec, b_dec, out);
    scan_kernel<<<BB, 1024>>>(dt, init_pos, init_vel, init_rot, out);
}

// round 4
// speedup vs baseline: 4.1092x; 4.1092x over previous
#include <cuda_runtime.h>
#include <cuda_bf16.h>

#define BB 8
#define FF 16384
#define HH 256
#define NROWS (BB*FF)
#define CHUNK 256
#define NCHB  (FF/CHUNK)        // 64 chunks per batch
#define NCHT  (BB*NCHB)         // 512 chunks total

typedef unsigned long long u64;

// ---------------- scratch (__device__ globals; no allocation) ----------------
__device__ float4 g_pq[NROWS];        // within-chunk inclusive quat prefix
__device__ float4 g_cq[NCHT];         // per-chunk quat product
__device__ float4 g_cpre[NCHT];       // per-chunk exclusive quat prefix (incl q0)
__device__ float  g_cacc[NROWS*3];    // corrected acc
__device__ float  g_eTSC[7*(size_t)NROWS]; // SoA: k*NROWS+e, within-chunk inclusive TSC
__device__ float  g_cTSC[NCHT*7];     // per-chunk TSC summary
__device__ float  g_cstart[NCHT*6];   // per-chunk (pos,vel) start state

// ---------------- packed f32x2 helpers ----------------
__device__ __forceinline__ u64 pk2(float lo, float hi) {
    u64 r; asm("mov.b64 %0,{%1,%2};" : "=l"(r) : "f"(lo), "f"(hi)); return r;
}
__device__ __forceinline__ void upk2(u64 v, float& lo, float& hi) {
    asm("mov.b64 {%0,%1},%2;" : "=f"(lo), "=f"(hi) : "l"(v));
}
__device__ __forceinline__ u64 ffma2(u64 a, u64 b, u64 c) {
    u64 r; asm("fma.rn.f32x2 %0,%1,%2,%3;" : "=l"(r) : "l"(a), "l"(b), "l"(c)); return r;
}
__device__ __forceinline__ u64 fmul2(u64 a, u64 b) {
    u64 r; asm("mul.rn.f32x2 %0,%1,%2;" : "=l"(r) : "l"(a), "l"(b)); return r;
}
__device__ __forceinline__ float ex2a(float x) {
    float r; asm("ex2.approx.f32 %0,%1;" : "=f"(r) : "f"(x)); return r;
}
__device__ __forceinline__ float rcpa(float x) {
    float r; asm("rcp.approx.f32 %0,%1;" : "=f"(r) : "f"(x)); return r;
}

// quaternion as float4: .x=w, .y..w = vector
__device__ __forceinline__ float4 qmul(float4 q, float4 p) {
    float4 r;
    r.x = q.x*p.x - q.y*p.y - q.z*p.z - q.w*p.w;
    r.y = q.x*p.y + p.x*q.y + (q.z*p.w - q.w*p.z);
    r.z = q.x*p.z + p.x*q.z + (q.w*p.y - q.y*p.w);
    r.w = q.x*p.w + p.x*q.w + (q.y*p.z - q.z*p.y);
    return r;
}

// ---------------------------------------------------------------------------
// K1: MLP (packed f32x2, h-pairs) + delta-quat + within-chunk quat scan
// grid = 512 blocks of 256 threads; block b == chunk b (256 consecutive rows)
// ---------------------------------------------------------------------------
__global__ void __launch_bounds__(256)
mlp_kernel(const float* __restrict__ acc, const float* __restrict__ gyro,
           const float* __restrict__ dt,
           const float* __restrict__ W_enc, const float* __restrict__ b_enc,
           const float* __restrict__ W_dec, const float* __restrict__ b_dec,
           float* __restrict__ out)
{
    // s_w[p*16 + 0..5]  = packed W_enc[k][2p],W_enc[k][2p+1]
    // s_w[p*16 + 6]     = packed b_enc pair
    // s_w[p*16 + 7..12] = packed W_dec[2p][k],W_dec[2p+1][k]
    __shared__ __align__(16) u64 s_w[128*16];
    __shared__ __align__(16) float4 s_q[256];
    int tid = threadIdx.x;

    if (tid < 128) {
        int p = tid;
        #pragma unroll
        for (int k = 0; k < 6; k++) {
            const float2 v = reinterpret_cast<const float2*>(W_enc + k*HH)[p];
            s_w[p*16 + k] = pk2(v.x, v.y);
        }
        const float2 bb = reinterpret_cast<const float2*>(b_enc)[p];
        s_w[p*16 + 6] = pk2(bb.x, bb.y);
        #pragma unroll
        for (int k = 0; k < 6; k++) {
            s_w[p*16 + 7 + k] = pk2(W_dec[(2*p)*6 + k], W_dec[(2*p+1)*6 + k]);
        }
        s_w[p*16 + 13] = 0; s_w[p*16 + 14] = 0; s_w[p*16 + 15] = 0;
    }
    __syncthreads();

    int r = blockIdx.x * 256 + tid;
    float x0 = acc[r*3+0], x1 = acc[r*3+1], x2 = acc[r*3+2];
    float x3 = gyro[r*3+0], x4 = gyro[r*3+1], x5 = gyro[r*3+2];
    u64 X0 = pk2(x0,x0), X1 = pk2(x1,x1), X2 = pk2(x2,x2);
    u64 X3 = pk2(x3,x3), X4 = pk2(x4,x4), X5 = pk2(x5,x5);

    const float CEXPc = 2.0f * 0.7978845608028654f * 1.4426950408889634f;
    u64 ONE2 = pk2(1.0f, 1.0f);
    u64 C044 = pk2(0.044715f, 0.044715f);
    u64 CEXP = pk2(CEXPc, CEXPc);
    u64 NEG1 = pk2(-1.0f, -1.0f);

    u64 a0 = 0, a1 = 0, a2 = 0, a3 = 0, a4 = 0, a5 = 0; // 0 == packed (0,0)

    #pragma unroll 4
    for (int p = 0; p < 128; p++) {
        const ulonglong2* q = reinterpret_cast<const ulonglong2*>(s_w + p*16);
        ulonglong2 q0 = q[0], q1 = q[1], q2 = q[2], q3 = q[3], q4 = q[4], q5 = q[5];
        u64 dec5 = reinterpret_cast<const u64*>(s_w + p*16)[12];

        u64 pre = q3.x;                 // bias pair
        pre = ffma2(q0.x, X0, pre);
        pre = ffma2(q0.y, X1, pre);
        pre = ffma2(q1.x, X2, pre);
        pre = ffma2(q1.y, X3, pre);
        pre = ffma2(q2.x, X4, pre);
        pre = ffma2(q2.y, X5, pre);

        // gelu(tanh): feat = pre * (1 - 1/(exp(2u)+1)), u = 0.79788456*(pre+0.044715 pre^3)
        u64 s2  = fmul2(pre, pre);
        u64 t2  = ffma2(s2, C044, ONE2);
        u64 in2 = fmul2(pre, t2);
        u64 up2 = fmul2(in2, CEXP);     // log2-domain: exp(2u) = 2^(up)
        float u0f, u1f; upk2(up2, u0f, u1f);
        float e0 = ex2a(u0f), e1 = ex2a(u1f);
        float r0 = rcpa(e0 + 1.0f), r1 = rcpa(e1 + 1.0f);
        u64 om  = ffma2(pk2(r0, r1), NEG1, ONE2);   // 1 - r
        u64 ft  = fmul2(pre, om);

        a0 = ffma2(ft, q3.y, a0);
        a1 = ffma2(ft, q4.x, a1);
        a2 = ffma2(ft, q4.y, a2);
        a3 = ffma2(ft, q5.x, a3);
        a4 = ffma2(ft, q5.y, a4);
        a5 = ffma2(ft, dec5, a5);
    }

    float lo, hi, c0, c1, c2, c3, c4, c5;
    upk2(a0, lo, hi); c0 = lo + hi + __ldg(&b_dec[0]);
    upk2(a1, lo, hi); c1 = lo + hi + __ldg(&b_dec[1]);
    upk2(a2, lo, hi); c2 = lo + hi + __ldg(&b_dec[2]);
    upk2(a3, lo, hi); c3 = lo + hi + __ldg(&b_dec[3]);
    upk2(a4, lo, hi); c4 = lo + hi + __ldg(&b_dec[4]);
    upk2(a5, lo, hi); c5 = lo + hi + __ldg(&b_dec[5]);

    size_t ob = (size_t)r * 16;
    out[ob+10] = c0; out[ob+11] = c1; out[ob+12] = c2;
    out[ob+13] = c3; out[ob+14] = c4; out[ob+15] = c5;

    g_cacc[r*3+0] = c0 + x0;
    g_cacc[r*3+1] = c1 + x1;
    g_cacc[r*3+2] = c2 + x2;

    // delta quaternion: quat_exp(corrected_gyro * dt)
    float dtv = dt[r];
    float v0 = (c3 + x3) * dtv;
    float v1 = (c4 + x4) * dtv;
    float v2 = (c5 + x5) * dtv;
    float tt2 = v0*v0 + v1*v1 + v2*v2;
    float theta = sqrtf(tt2 + 1e-16f);
    float half  = 0.5f * theta;
    float w  = cosf(half);
    float sc = (tt2 < 1e-12f) ? (0.5f - tt2 * (1.0f/48.0f)) : (sinf(half) / theta);
    float4 dq = make_float4(w, v0*sc, v1*sc, v2*sc);

    // within-chunk inclusive quat prefix scan (Hillis-Steele, 8 levels)
    s_q[tid] = dq;
    __syncthreads();
    float4 v = dq;
    #pragma unroll
    for (int off = 1; off < 256; off <<= 1) {
        v = s_q[tid];
        if (tid >= off) v = qmul(s_q[tid - off], v);
        __syncthreads();
        s_q[tid] = v;
        __syncthreads();
    }
    g_pq[r] = v;
    if (tid == 255) g_cq[blockIdx.x] = v;
}

// ---------------------------------------------------------------------------
// K2: scan chunk quat products per batch -> exclusive prefix (with q0 folded)
// grid = 8, block = 64
// ---------------------------------------------------------------------------
__global__ void __launch_bounds__(64)
chunkq_kernel(const float* __restrict__ init_rot)
{
    __shared__ __align__(16) float4 s[64];
    int b = blockIdx.x, t = threadIdx.x;
    s[t] = g_cq[b*NCHB + t];
    __syncthreads();
    float4 v;
    #pragma unroll
    for (int off = 1; off < 64; off <<= 1) {
        v = s[t];
        if (t >= off) v = qmul(s[t - off], v);
        __syncthreads();
        s[t] = v;
        __syncthreads();
    }
    float4 q0 = make_float4(init_rot[b*4+0], init_rot[b*4+1],
                            init_rot[b*4+2], init_rot[b*4+3]);
    float4 pre = (t == 0) ? q0 : qmul(q0, s[t-1]);
    g_cpre[b*NCHB + t] = pre;
}

// ---------------------------------------------------------------------------
// K3: per-element world accel + rot output + within-chunk TSC scan
// grid = 512 (chunk), block = 256
// ---------------------------------------------------------------------------
__global__ void __launch_bounds__(256)
accel_kernel(const float* __restrict__ dt, float* __restrict__ out)
{
    __shared__ __align__(16) float4 spq[256];
    __shared__ float st[256*7];
    int c = blockIdx.x, j = threadIdx.x;
    int e = c*256 + j;

    float4 cpre = g_cpre[c];
    float4 myq = g_pq[e];
    spq[j] = myq;
    __syncthreads();

    // exclusive orientation (pre-step), normalized
    float4 Ee = (j == 0) ? cpre : qmul(cpre, spq[j-1]);
    float rn = rsqrtf(Ee.x*Ee.x + Ee.y*Ee.y + Ee.z*Ee.z + Ee.w*Ee.w);
    float qw = Ee.x*rn, q1 = Ee.y*rn, q2 = Ee.z*rn, q3 = Ee.w*rn;

    float v1 = g_cacc[e*3+0], v2 = g_cacc[e*3+1], v3 = g_cacc[e*3+2];
    float t1 = (q2*v3 - q3*v2) + qw*v1;
    float t2 = (q3*v1 - q1*v3) + qw*v2;
    float t3 = (q1*v2 - q2*v1) + qw*v3;
    float a0 = v1 + 2.0f*(q2*t3 - q3*t2);
    float a1 = v2 + 2.0f*(q3*t1 - q1*t3);
    float a2 = v3 + 2.0f*(q1*t2 - q2*t1) - 9.81007f;

    // inclusive orientation -> rot output
    float4 Ei = qmul(cpre, myq);
    float rn2 = rsqrtf(Ei.x*Ei.x + Ei.y*Ei.y + Ei.z*Ei.z + Ei.w*Ei.w);
    size_t ob = (size_t)e * 16;
    out[ob+6] = Ei.x*rn2; out[ob+7] = Ei.y*rn2;
    out[ob+8] = Ei.z*rn2; out[ob+9] = Ei.w*rn2;

    // per-element TSC: T=dt, S=a*dt, C=0.5*a*dt^2 ; combine: C = Cl+Cr+Sl*Tr
    float dtv = dt[e];
    float hd = 0.5f*dtv*dtv;
    float T = dtv, S0 = a0*dtv, S1 = a1*dtv, S2 = a2*dtv;
    float C0 = a0*hd, C1 = a1*hd, C2 = a2*hd;

    st[j*7+0]=T; st[j*7+1]=S0; st[j*7+2]=S1; st[j*7+3]=S2;
    st[j*7+4]=C0; st[j*7+5]=C1; st[j*7+6]=C2;
    __syncthreads();
    #pragma unroll
    for (int off = 1; off < 256; off <<= 1) {
        float rT = st[j*7+0];
        float rS0 = st[j*7+1], rS1 = st[j*7+2], rS2 = st[j*7+3];
        float rC0 = st[j*7+4], rC1 = st[j*7+5], rC2 = st[j*7+6];
        if (j >= off) {
            int l = (j - off)*7;
            float lT = st[l+0];
            float lS0 = st[l+1], lS1 = st[l+2], lS2 = st[l+3];
            float lC0 = st[l+4], lC1 = st[l+5], lC2 = st[l+6];
            rC0 = lC0 + rC0 + lS0*rT;
            rC1 = lC1 + rC1 + lS1*rT;
            rC2 = lC2 + rC2 + lS2*rT;
            rS0 += lS0; rS1 += lS1; rS2 += lS2;
            rT += lT;
        }
        __syncthreads();
        st[j*7+0]=rT; st[j*7+1]=rS0; st[j*7+2]=rS1; st[j*7+3]=rS2;
        st[j*7+4]=rC0; st[j*7+5]=rC1; st[j*7+6]=rC2;
        __syncthreads();
    }

    float fT = st[j*7+0];
    float fS0 = st[j*7+1], fS1 = st[j*7+2], fS2 = st[j*7+3];
    float fC0 = st[j*7+4], fC1 = st[j*7+5], fC2 = st[j*7+6];
    g_eTSC[0*(size_t)NROWS + e] = fT;
    g_eTSC[1*(size_t)NROWS + e] = fS0;
    g_eTSC[2*(size_t)NROWS + e] = fS1;
    g_eTSC[3*(size_t)NROWS + e] = fS2;
    g_eTSC[4*(size_t)NROWS + e] = fC0;
    g_eTSC[5*(size_t)NROWS + e] = fC1;
    g_eTSC[6*(size_t)NROWS + e] = fC2;
    if (j == 255) {
        g_cTSC[c*7+0]=fT; g_cTSC[c*7+1]=fS0; g_cTSC[c*7+2]=fS1; g_cTSC[c*7+3]=fS2;
        g_cTSC[c*7+4]=fC0; g_cTSC[c*7+5]=fC1; g_cTSC[c*7+6]=fC2;
    }
}

// ---------------------------------------------------------------------------
// K4: scan chunk TSC per batch -> per-chunk (pos,vel) start state
// grid = 8, block = 64
// ---------------------------------------------------------------------------
__global__ void __launch_bounds__(64)
chunktsc_kernel(const float* __restrict__ init_pos, const float* __restrict__ init_vel)
{
    __shared__ float st[64*7];
    int b = blockIdx.x, t = threadIdx.x;
    int c = b*NCHB + t;
    #pragma unroll
    for (int k = 0; k < 7; k++) st[t*7+k] = g_cTSC[c*7+k];
    __syncthreads();
    #pragma unroll
    for (int off = 1; off < 64; off <<= 1) {
        float rT = st[t*7+0];
        float rS0 = st[t*7+1], rS1 = st[t*7+2], rS2 = st[t*7+3];
        float rC0 = st[t*7+4], rC1 = st[t*7+5], rC2 = st[t*7+6];
        if (t >= off) {
            int l = (t - off)*7;
            rC0 = st[l+4] + rC0 + st[l+1]*rT;
            rC1 = st[l+5] + rC1 + st[l+2]*rT;
            rC2 = st[l+6] + rC2 + st[l+3]*rT;
            rS0 += st[l+1]; rS1 += st[l+2]; rS2 += st[l+3];
            rT += st[l+0];
        }
        __syncthreads();
        st[t*7+0]=rT; st[t*7+1]=rS0; st[t*7+2]=rS1; st[t*7+3]=rS2;
        st[t*7+4]=rC0; st[t*7+5]=rC1; st[t*7+6]=rC2;
        __syncthreads();
    }
    float iv0 = init_vel[b*3+0], iv1 = init_vel[b*3+1], iv2 = init_vel[b*3+2];
    float ip0 = init_pos[b*3+0], ip1 = init_pos[b*3+1], ip2 = init_pos[b*3+2];
    float Te=0.f, Se0=0.f,Se1=0.f,Se2=0.f, Ce0=0.f,Ce1=0.f,Ce2=0.f;
    if (t > 0) {
        int l = (t-1)*7;
        Te = st[l+0]; Se0 = st[l+1]; Se1 = st[l+2]; Se2 = st[l+3];
        Ce0 = st[l+4]; Ce1 = st[l+5]; Ce2 = st[l+6];
    }
    g_cstart[c*6+0] = ip0 + iv0*Te + Ce0;
    g_cstart[c*6+1] = ip1 + iv1*Te + Ce1;
    g_cstart[c*6+2] = ip2 + iv2*Te + Ce2;
    g_cstart[c*6+3] = iv0 + Se0;
    g_cstart[c*6+4] = iv1 + Se1;
    g_cstart[c*6+5] = iv2 + Se2;
}

// ---------------------------------------------------------------------------
// K5: final per-element pos/vel
// grid = 512, block = 256
// ---------------------------------------------------------------------------
__global__ void __launch_bounds__(256)
posvel_kernel(float* __restrict__ out)
{
    int c = blockIdx.x, j = threadIdx.x;
    int e = c*256 + j;
    float ps0 = g_cstart[c*6+0], ps1 = g_cstart[c*6+1], ps2 = g_cstart[c*6+2];
    float vs0 = g_cstart[c*6+3], vs1 = g_cstart[c*6+4], vs2 = g_cstart[c*6+5];
    float T  = g_eTSC[0*(size_t)NROWS + e];
    float S0 = g_eTSC[1*(size_t)NROWS + e];
    float S1 = g_eTSC[2*(size_t)NROWS + e];
    float S2 = g_eTSC[3*(size_t)NROWS + e];
    float C0 = g_eTSC[4*(size_t)NROWS + e];
    float C1 = g_eTSC[5*(size_t)NROWS + e];
    float C2 = g_eTSC[6*(size_t)NROWS + e];
    size_t ob = (size_t)e * 16;
    out[ob+0] = ps0 + vs0*T + C0;
    out[ob+1] = ps1 + vs1*T + C1;
    out[ob+2] = ps2 + vs2*T + C2;
    out[ob+3] = vs0 + S0;
    out[ob+4] = vs1 + S1;
    out[ob+5] = vs2 + S2;
}

// ---------------------------------------------------------------------------
extern "C" void kernel_launch(void* const* d_in, const int* in_sizes, int n_in,
                              void* d_out, int out_size)
{
    const float* acc      = (const float*)d_in[0];
    const float* gyro     = (const float*)d_in[1];
    const float* dt       = (const float*)d_in[2];
    const float* init_pos = (const float*)d_in[3];
    const float* init_vel = (const float*)d_in[4];
    const float* init_rot = (const float*)d_in[5];
    const float* W_enc    = (const float*)d_in[6];
    const float* b_enc    = (const float*)d_in[7];
    const float* W_dec    = (const float*)d_in[8];
    const float* b_dec    = (const float*)d_in[9];
    float* out = (float*)d_out;

    mlp_kernel<<<NCHT, 256>>>(acc, gyro, dt, W_enc, b_enc, W_dec, b_dec, out);
    chunkq_kernel<<<BB, 64>>>(init_rot);
    accel_kernel<<<NCHT, 256>>>(dt, out);
    chunktsc_kernel<<<BB, 64>>>(init_pos, init_vel);
    posvel_kernel<<<NCHT, 256>>>(out);
}

// round 5
// speedup vs baseline: 5.0513x; 1.2293x over previous
#include <cuda_runtime.h>
#include <cuda_bf16.h>

#define BB 8
#define FF 16384
#define HH 256
#define NROWS (BB*FF)
#define CHUNK 256
#define NCHB  (FF/CHUNK)        // 64 chunks per batch
#define NCHT  (BB*NCHB)         // 512 chunks total

typedef unsigned long long u64;

// ---------------- scratch (__device__ globals; no allocation) ----------------
__device__ float4 g_pq[NROWS];        // within-chunk inclusive quat prefix
__device__ float4 g_cq[NCHT];         // per-chunk quat product
__device__ float4 g_cpre[NCHT];       // per-chunk exclusive quat prefix (incl q0)
__device__ float  g_cacc[NROWS*3];    // corrected acc
__device__ float  g_eTSC[7*(size_t)NROWS]; // SoA: k*NROWS+e, within-chunk inclusive TSC
__device__ float  g_cTSC[NCHT*7];     // per-chunk TSC summary
__device__ float  g_cstart[NCHT*6];   // per-chunk (pos,vel) start state
__device__ unsigned int g_ctr1 = 0;   // last-block counters (reset after use)
__device__ unsigned int g_ctr2 = 0;

// ---------------- packed f32x2 helpers ----------------
__device__ __forceinline__ u64 pk2(float lo, float hi) {
    u64 r; asm("mov.b64 %0,{%1,%2};" : "=l"(r) : "f"(lo), "f"(hi)); return r;
}
__device__ __forceinline__ void upk2(u64 v, float& lo, float& hi) {
    asm("mov.b64 {%0,%1},%2;" : "=f"(lo), "=f"(hi) : "l"(v));
}
__device__ __forceinline__ u64 ffma2(u64 a, u64 b, u64 c) {
    u64 r; asm("fma.rn.f32x2 %0,%1,%2,%3;" : "=l"(r) : "l"(a), "l"(b), "l"(c)); return r;
}
__device__ __forceinline__ u64 fmul2(u64 a, u64 b) {
    u64 r; asm("mul.rn.f32x2 %0,%1,%2;" : "=l"(r) : "l"(a), "l"(b)); return r;
}
__device__ __forceinline__ float tanha(float x) {
    float r; asm("tanh.approx.f32 %0,%1;" : "=f"(r) : "f"(x)); return r;
}

// quaternion as float4: .x=w, .y..w = vector
__device__ __forceinline__ float4 qmul(float4 q, float4 p) {
    float4 r;
    r.x = q.x*p.x - q.y*p.y - q.z*p.z - q.w*p.w;
    r.y = q.x*p.y + p.x*q.y + (q.z*p.w - q.w*p.z);
    r.z = q.x*p.z + p.x*q.z + (q.w*p.y - q.y*p.w);
    r.w = q.x*p.w + p.x*q.w + (q.y*p.z - q.z*p.y);
    return r;
}

__device__ __forceinline__ float4 shfl_up_q(float4 v, int off) {
    float4 r;
    r.x = __shfl_up_sync(0xffffffffu, v.x, off);
    r.y = __shfl_up_sync(0xffffffffu, v.y, off);
    r.z = __shfl_up_sync(0xffffffffu, v.z, off);
    r.w = __shfl_up_sync(0xffffffffu, v.w, off);
    return r;
}

// TSC state: T, S[3], C[3]; combine(l,r): C=Cl+Cr+Sl*Tr; S=Sl+Sr; T=Tl+Tr
struct TSC { float T, S0, S1, S2, C0, C1, C2; };
__device__ __forceinline__ TSC tsc_comb(const TSC& l, const TSC& r) {
    TSC o;
    o.C0 = l.C0 + r.C0 + l.S0*r.T;
    o.C1 = l.C1 + r.C1 + l.S1*r.T;
    o.C2 = l.C2 + r.C2 + l.S2*r.T;
    o.S0 = l.S0 + r.S0; o.S1 = l.S1 + r.S1; o.S2 = l.S2 + r.S2;
    o.T  = l.T + r.T;
    return o;
}
__device__ __forceinline__ TSC shfl_up_tsc(const TSC& v, int off) {
    TSC r;
    r.T  = __shfl_up_sync(0xffffffffu, v.T, off);
    r.S0 = __shfl_up_sync(0xffffffffu, v.S0, off);
    r.S1 = __shfl_up_sync(0xffffffffu, v.S1, off);
    r.S2 = __shfl_up_sync(0xffffffffu, v.S2, off);
    r.C0 = __shfl_up_sync(0xffffffffu, v.C0, off);
    r.C1 = __shfl_up_sync(0xffffffffu, v.C1, off);
    r.C2 = __shfl_up_sync(0xffffffffu, v.C2, off);
    return r;
}

// ---------------------------------------------------------------------------
// K1: MLP (f32x2, h-pairs, tanh.approx GELU) + delta-quat + chunk quat scan
//     + last-block: cross-chunk quat scan (replaces old K2)
// grid = 512 blocks of 256 threads; block == chunk
// ---------------------------------------------------------------------------
__global__ void __launch_bounds__(256)
mlp_kernel(const float* __restrict__ acc, const float* __restrict__ gyro,
           const float* __restrict__ dt, const float* __restrict__ init_rot,
           const float* __restrict__ W_enc, const float* __restrict__ b_enc,
           const float* __restrict__ W_dec, const float* __restrict__ b_dec,
           float* __restrict__ out)
{
    __shared__ __align__(16) u64 s_w[128*16];
    __shared__ __align__(16) float4 s_wq[8];   // warp quat totals
    __shared__ bool s_last;
    int tid = threadIdx.x;
    int lane = tid & 31, wid = tid >> 5;

    if (tid < 128) {
        int p = tid;
        #pragma unroll
        for (int k = 0; k < 6; k++) {
            const float2 v = reinterpret_cast<const float2*>(W_enc + k*HH)[p];
            s_w[p*16 + k] = pk2(v.x, v.y);
        }
        const float2 bb = reinterpret_cast<const float2*>(b_enc)[p];
        s_w[p*16 + 6] = pk2(bb.x, bb.y);
        #pragma unroll
        for (int k = 0; k < 6; k++) {
            s_w[p*16 + 7 + k] = pk2(W_dec[(2*p)*6 + k], W_dec[(2*p+1)*6 + k]);
        }
        s_w[p*16 + 13] = 0; s_w[p*16 + 14] = 0; s_w[p*16 + 15] = 0;
    }
    __syncthreads();

    int r = blockIdx.x * 256 + tid;
    float x0 = acc[r*3+0], x1 = acc[r*3+1], x2 = acc[r*3+2];
    float x3 = gyro[r*3+0], x4 = gyro[r*3+1], x5 = gyro[r*3+2];
    u64 X0 = pk2(x0,x0), X1 = pk2(x1,x1), X2 = pk2(x2,x2);
    u64 X3 = pk2(x3,x3), X4 = pk2(x4,x4), X5 = pk2(x5,x5);

    u64 CU1 = pk2(0.7978845608028654f, 0.7978845608028654f);
    u64 CU3 = pk2(0.035677408136300125f, 0.035677408136300125f);
    u64 HLF = pk2(0.5f, 0.5f);

    u64 a0 = 0, a1 = 0, a2 = 0, a3 = 0, a4 = 0, a5 = 0;

    #pragma unroll 4
    for (int p = 0; p < 128; p++) {
        const ulonglong2* q = reinterpret_cast<const ulonglong2*>(s_w + p*16);
        ulonglong2 q0 = q[0], q1 = q[1], q2 = q[2], q3 = q[3], q4 = q[4], q5 = q[5];
        u64 dec5 = reinterpret_cast<const u64*>(s_w + p*16)[12];

        u64 pre = q3.x;
        pre = ffma2(q0.x, X0, pre);
        pre = ffma2(q0.y, X1, pre);
        pre = ffma2(q1.x, X2, pre);
        pre = ffma2(q1.y, X3, pre);
        pre = ffma2(q2.x, X4, pre);
        pre = ffma2(q2.y, X5, pre);

        // gelu(tanh): u = pre*(c1 + c3*pre^2); feat = pre*(0.5 + 0.5*tanh(u))
        u64 s2 = fmul2(pre, pre);
        u64 t2 = ffma2(s2, CU3, CU1);
        u64 up = fmul2(pre, t2);
        float u0f, u1f; upk2(up, u0f, u1f);
        u64 th2 = pk2(tanha(u0f), tanha(u1f));
        u64 om  = ffma2(th2, HLF, HLF);
        u64 ft  = fmul2(pre, om);

        a0 = ffma2(ft, q3.y, a0);
        a1 = ffma2(ft, q4.x, a1);
        a2 = ffma2(ft, q4.y, a2);
        a3 = ffma2(ft, q5.x, a3);
        a4 = ffma2(ft, q5.y, a4);
        a5 = ffma2(ft, dec5, a5);
    }

    float lo, hi, c0, c1, c2, c3, c4, c5;
    upk2(a0, lo, hi); c0 = lo + hi + __ldg(&b_dec[0]);
    upk2(a1, lo, hi); c1 = lo + hi + __ldg(&b_dec[1]);
    upk2(a2, lo, hi); c2 = lo + hi + __ldg(&b_dec[2]);
    upk2(a3, lo, hi); c3 = lo + hi + __ldg(&b_dec[3]);
    upk2(a4, lo, hi); c4 = lo + hi + __ldg(&b_dec[4]);
    upk2(a5, lo, hi); c5 = lo + hi + __ldg(&b_dec[5]);

    size_t ob = (size_t)r * 16;
    out[ob+10] = c0; out[ob+11] = c1; out[ob+12] = c2;
    out[ob+13] = c3; out[ob+14] = c4; out[ob+15] = c5;

    g_cacc[r*3+0] = c0 + x0;
    g_cacc[r*3+1] = c1 + x1;
    g_cacc[r*3+2] = c2 + x2;

    // delta quaternion: quat_exp(corrected_gyro * dt)
    float dtv = dt[r];
    float v0 = (c3 + x3) * dtv;
    float v1 = (c4 + x4) * dtv;
    float v2 = (c5 + x5) * dtv;
    float tt2 = v0*v0 + v1*v1 + v2*v2;
    float theta = sqrtf(tt2 + 1e-16f);
    float half  = 0.5f * theta;
    float w  = cosf(half);
    float sc = (tt2 < 1e-12f) ? (0.5f - tt2 * (1.0f/48.0f)) : (sinf(half) / theta);
    float4 v = make_float4(w, v0*sc, v1*sc, v2*sc);

    // within-chunk inclusive quat scan: warp shuffle + warp-total prefix
    #pragma unroll
    for (int off = 1; off < 32; off <<= 1) {
        float4 u = shfl_up_q(v, off);
        if (lane >= off) v = qmul(u, v);
    }
    if (lane == 31) s_wq[wid] = v;
    __syncthreads();
    float4 wp = make_float4(1.f, 0.f, 0.f, 0.f);
    for (int wI = 0; wI < wid; wI++) wp = qmul(wp, s_wq[wI]);
    float4 incl = qmul(wp, v);
    g_pq[r] = incl;
    if (tid == 255) g_cq[blockIdx.x] = incl;

    // ---- last-block: cross-chunk exclusive quat prefix for all batches ----
    __threadfence();
    __syncthreads();
    if (tid == 0) s_last = (atomicAdd(&g_ctr1, 1u) == gridDim.x - 1);
    __syncthreads();
    if (s_last) {
        __threadfence();
        int b = wid;                 // 8 warps == 8 batches
        float4 d0 = g_cq[b*NCHB + 2*lane];
        float4 d1 = g_cq[b*NCHB + 2*lane + 1];
        float4 pr = qmul(d0, d1);
        #pragma unroll
        for (int off = 1; off < 32; off <<= 1) {
            float4 u = shfl_up_q(pr, off);
            if (lane >= off) pr = qmul(u, pr);
        }
        float4 ex = shfl_up_q(pr, 1);   // exclusive lane prefix
        float4 q0 = make_float4(init_rot[b*4+0], init_rot[b*4+1],
                                init_rot[b*4+2], init_rot[b*4+3]);
        float4 pre0 = (lane == 0) ? q0 : qmul(q0, ex);
        float4 pre1 = qmul(pre0, d0);
        g_cpre[b*NCHB + 2*lane]     = pre0;
        g_cpre[b*NCHB + 2*lane + 1] = pre1;
        __syncthreads();
        if (tid == 0) g_ctr1 = 0;   // reset for next graph replay
    }
}

// ---------------------------------------------------------------------------
// K2: world accel + rot out + within-chunk TSC scan
//     + last-block: cross-chunk TSC scan -> g_cstart (replaces old K4)
// grid = 512, block = 256
// ---------------------------------------------------------------------------
__global__ void __launch_bounds__(256)
accel_kernel(const float* __restrict__ dt,
             const float* __restrict__ init_pos, const float* __restrict__ init_vel,
             float* __restrict__ out)
{
    __shared__ TSC s_wt[8];
    __shared__ bool s_last;
    int c = blockIdx.x, j = threadIdx.x;
    int lane = j & 31, wid = j >> 5;
    int e = c*256 + j;

    float4 cpre = g_cpre[c];
    float4 myq = g_pq[e];
    // exclusive (pre-step) orientation
    float4 Ee = (j == 0) ? cpre : qmul(cpre, g_pq[e-1]);
    float rn = rsqrtf(Ee.x*Ee.x + Ee.y*Ee.y + Ee.z*Ee.z + Ee.w*Ee.w);
    float qw = Ee.x*rn, q1 = Ee.y*rn, q2 = Ee.z*rn, q3 = Ee.w*rn;

    float v1 = g_cacc[e*3+0], v2 = g_cacc[e*3+1], v3 = g_cacc[e*3+2];
    float t1 = (q2*v3 - q3*v2) + qw*v1;
    float t2 = (q3*v1 - q1*v3) + qw*v2;
    float t3 = (q1*v2 - q2*v1) + qw*v3;
    float a0 = v1 + 2.0f*(q2*t3 - q3*t2);
    float a1 = v2 + 2.0f*(q3*t1 - q1*t3);
    float a2 = v3 + 2.0f*(q1*t2 - q2*t1) - 9.81007f;

    // inclusive orientation -> rot output
    float4 Ei = qmul(cpre, myq);
    float rn2 = rsqrtf(Ei.x*Ei.x + Ei.y*Ei.y + Ei.z*Ei.z + Ei.w*Ei.w);
    size_t ob = (size_t)e * 16;
    out[ob+6] = Ei.x*rn2; out[ob+7] = Ei.y*rn2;
    out[ob+8] = Ei.z*rn2; out[ob+9] = Ei.w*rn2;

    // per-element TSC, then block inclusive scan (shuffle + warp totals)
    float dtv = dt[e];
    float hd = 0.5f*dtv*dtv;
    TSC v; v.T = dtv;
    v.S0 = a0*dtv; v.S1 = a1*dtv; v.S2 = a2*dtv;
    v.C0 = a0*hd;  v.C1 = a1*hd;  v.C2 = a2*hd;

    #pragma unroll
    for (int off = 1; off < 32; off <<= 1) {
        TSC u = shfl_up_tsc(v, off);
        if (lane >= off) v = tsc_comb(u, v);
    }
    if (lane == 31) s_wt[wid] = v;
    __syncthreads();
    TSC wp; wp.T=0.f; wp.S0=0.f; wp.S1=0.f; wp.S2=0.f; wp.C0=0.f; wp.C1=0.f; wp.C2=0.f;
    for (int wI = 0; wI < wid; wI++) wp = tsc_comb(wp, s_wt[wI]);
    TSC incl = tsc_comb(wp, v);

    g_eTSC[0*(size_t)NROWS + e] = incl.T;
    g_eTSC[1*(size_t)NROWS + e] = incl.S0;
    g_eTSC[2*(size_t)NROWS + e] = incl.S1;
    g_eTSC[3*(size_t)NROWS + e] = incl.S2;
    g_eTSC[4*(size_t)NROWS + e] = incl.C0;
    g_eTSC[5*(size_t)NROWS + e] = incl.C1;
    g_eTSC[6*(size_t)NROWS + e] = incl.C2;
    if (j == 255) {
        g_cTSC[c*7+0]=incl.T;
        g_cTSC[c*7+1]=incl.S0; g_cTSC[c*7+2]=incl.S1; g_cTSC[c*7+3]=incl.S2;
        g_cTSC[c*7+4]=incl.C0; g_cTSC[c*7+5]=incl.C1; g_cTSC[c*7+6]=incl.C2;
    }

    // ---- last-block: cross-chunk TSC scan -> per-chunk start (pos, vel) ----
    __threadfence();
    __syncthreads();
    if (j == 0) s_last = (atomicAdd(&g_ctr2, 1u) == gridDim.x - 1);
    __syncthreads();
    if (s_last) {
        __threadfence();
        int b = wid;
        int c0i = b*NCHB + 2*lane, c1i = c0i + 1;
        TSC d0, d1;
        d0.T=g_cTSC[c0i*7+0]; d0.S0=g_cTSC[c0i*7+1]; d0.S1=g_cTSC[c0i*7+2]; d0.S2=g_cTSC[c0i*7+3];
        d0.C0=g_cTSC[c0i*7+4]; d0.C1=g_cTSC[c0i*7+5]; d0.C2=g_cTSC[c0i*7+6];
        d1.T=g_cTSC[c1i*7+0]; d1.S0=g_cTSC[c1i*7+1]; d1.S1=g_cTSC[c1i*7+2]; d1.S2=g_cTSC[c1i*7+3];
        d1.C0=g_cTSC[c1i*7+4]; d1.C1=g_cTSC[c1i*7+5]; d1.C2=g_cTSC[c1i*7+6];
        TSC pr = tsc_comb(d0, d1);
        #pragma unroll
        for (int off = 1; off < 32; off <<= 1) {
            TSC u = shfl_up_tsc(pr, off);
            if (lane >= off) pr = tsc_comb(u, pr);
        }
        TSC ex = shfl_up_tsc(pr, 1);
        if (lane == 0) { ex.T=0.f; ex.S0=0.f; ex.S1=0.f; ex.S2=0.f; ex.C0=0.f; ex.C1=0.f; ex.C2=0.f; }
        TSC ex1 = tsc_comb(ex, d0);   // exclusive prefix for chunk c1i
        float ip0 = init_pos[b*3+0], ip1 = init_pos[b*3+1], ip2 = init_pos[b*3+2];
        float iv0 = init_vel[b*3+0], iv1 = init_vel[b*3+1], iv2 = init_vel[b*3+2];
        g_cstart[c0i*6+0] = ip0 + iv0*ex.T + ex.C0;
        g_cstart[c0i*6+1] = ip1 + iv1*ex.T + ex.C1;
        g_cstart[c0i*6+2] = ip2 + iv2*ex.T + ex.C2;
        g_cstart[c0i*6+3] = iv0 + ex.S0;
        g_cstart[c0i*6+4] = iv1 + ex.S1;
        g_cstart[c0i*6+5] = iv2 + ex.S2;
        g_cstart[c1i*6+0] = ip0 + iv0*ex1.T + ex1.C0;
        g_cstart[c1i*6+1] = ip1 + iv1*ex1.T + ex1.C1;
        g_cstart[c1i*6+2] = ip2 + iv2*ex1.T + ex1.C2;
        g_cstart[c1i*6+3] = iv0 + ex1.S0;
        g_cstart[c1i*6+4] = iv1 + ex1.S1;
        g_cstart[c1i*6+5] = iv2 + ex1.S2;
        __syncthreads();
        if (j == 0) g_ctr2 = 0;
    }
}

// ---------------------------------------------------------------------------
// K3: final per-element pos/vel
// ---------------------------------------------------------------------------
__global__ void __launch_bounds__(256)
posvel_kernel(float* __restrict__ out)
{
    int c = blockIdx.x, j = threadIdx.x;
    int e = c*256 + j;
    float ps0 = g_cstart[c*6+0], ps1 = g_cstart[c*6+1], ps2 = g_cstart[c*6+2];
    float vs0 = g_cstart[c*6+3], vs1 = g_cstart[c*6+4], vs2 = g_cstart[c*6+5];
    float T  = g_eTSC[0*(size_t)NROWS + e];
    float S0 = g_eTSC[1*(size_t)NROWS + e];
    float S1 = g_eTSC[2*(size_t)NROWS + e];
    float S2 = g_eTSC[3*(size_t)NROWS + e];
    float C0 = g_eTSC[4*(size_t)NROWS + e];
    float C1 = g_eTSC[5*(size_t)NROWS + e];
    float C2 = g_eTSC[6*(size_t)NROWS + e];
    size_t ob = (size_t)e * 16;
    out[ob+0] = ps0 + vs0*T + C0;
    out[ob+1] = ps1 + vs1*T + C1;
    out[ob+2] = ps2 + vs2*T + C2;
    out[ob+3] = vs0 + S0;
    out[ob+4] = vs1 + S1;
    out[ob+5] = vs2 + S2;
}

// ---------------------------------------------------------------------------
extern "C" void kernel_launch(void* const* d_in, const int* in_sizes, int n_in,
                              void* d_out, int out_size)
{
    const float* acc      = (const float*)d_in[0];
    const float* gyro     = (const float*)d_in[1];
    const float* dt       = (const float*)d_in[2];
    const float* init_pos = (const float*)d_in[3];
    const float* init_vel = (const float*)d_in[4];
    const float* init_rot = (const float*)d_in[5];
    const float* W_enc    = (const float*)d_in[6];
    const float* b_enc    = (const float*)d_in[7];
    const float* W_dec    = (const float*)d_in[8];
    const float* b_dec    = (const float*)d_in[9];
    float* out = (float*)d_out;

    mlp_kernel<<<NCHT, 256>>>(acc, gyro, dt, init_rot, W_enc, b_enc, W_dec, b_dec, out);
    accel_kernel<<<NCHT, 256>>>(dt, init_pos, init_vel, out);
    posvel_kernel<<<NCHT, 256>>>(out);
}

// round 6
// speedup vs baseline: 5.4670x; 1.0823x over previous
#include <cuda_runtime.h>
#include <cuda_bf16.h>

#define BB 8
#define FF 16384
#define HH 256
#define NROWS (BB*FF)
#define CHUNK 256
#define NCHB  (FF/CHUNK)        // 64 chunks per batch
#define NCHT  (BB*NCHB)         // 512 chunks total

typedef unsigned long long u64;

// ---------------- scratch (__device__ globals; no allocation) ----------------
__device__ float4 g_pq[NROWS];        // within-chunk inclusive quat prefix
__device__ float4 g_cq[NCHT];         // per-chunk quat product
__device__ float4 g_cpre[NCHT];       // per-chunk exclusive quat prefix (incl q0)
__device__ float  g_cacc[NROWS*3];    // corrected acc
__device__ float  g_eTSC[7*(size_t)NROWS]; // SoA within-chunk inclusive TSC
__device__ float  g_cTSC[NCHT*7];     // per-chunk TSC summary
__device__ float  g_cstart[NCHT*6];   // per-chunk (pos,vel) start state
__device__ unsigned int g_ctr1 = 0;
__device__ unsigned int g_ctr2 = 0;

// ---------------- packed f32x2 helpers ----------------
__device__ __forceinline__ u64 pk2(float lo, float hi) {
    u64 r; asm("mov.b64 %0,{%1,%2};" : "=l"(r) : "f"(lo), "f"(hi)); return r;
}
__device__ __forceinline__ void upk2(u64 v, float& lo, float& hi) {
    asm("mov.b64 {%0,%1},%2;" : "=f"(lo), "=f"(hi) : "l"(v));
}
__device__ __forceinline__ u64 ffma2(u64 a, u64 b, u64 c) {
    u64 r; asm("fma.rn.f32x2 %0,%1,%2,%3;" : "=l"(r) : "l"(a), "l"(b), "l"(c)); return r;
}
__device__ __forceinline__ u64 fmul2(u64 a, u64 b) {
    u64 r; asm("mul.rn.f32x2 %0,%1,%2;" : "=l"(r) : "l"(a), "l"(b)); return r;
}
__device__ __forceinline__ float tanha(float x) {
    float r; asm("tanh.approx.f32 %0,%1;" : "=f"(r) : "f"(x)); return r;
}

// quaternion as float4: .x=w, .y..w = vector
__device__ __forceinline__ float4 qmul(float4 q, float4 p) {
    float4 r;
    r.x = q.x*p.x - q.y*p.y - q.z*p.z - q.w*p.w;
    r.y = q.x*p.y + p.x*q.y + (q.z*p.w - q.w*p.z);
    r.z = q.x*p.z + p.x*q.z + (q.w*p.y - q.y*p.w);
    r.w = q.x*p.w + p.x*q.w + (q.y*p.z - q.z*p.y);
    return r;
}

__device__ __forceinline__ float4 shfl_up_q(float4 v, int off) {
    float4 r;
    r.x = __shfl_up_sync(0xffffffffu, v.x, off);
    r.y = __shfl_up_sync(0xffffffffu, v.y, off);
    r.z = __shfl_up_sync(0xffffffffu, v.z, off);
    r.w = __shfl_up_sync(0xffffffffu, v.w, off);
    return r;
}

struct TSC { float T, S0, S1, S2, C0, C1, C2; };
__device__ __forceinline__ TSC tsc_comb(const TSC& l, const TSC& r) {
    TSC o;
    o.C0 = l.C0 + r.C0 + l.S0*r.T;
    o.C1 = l.C1 + r.C1 + l.S1*r.T;
    o.C2 = l.C2 + r.C2 + l.S2*r.T;
    o.S0 = l.S0 + r.S0; o.S1 = l.S1 + r.S1; o.S2 = l.S2 + r.S2;
    o.T  = l.T + r.T;
    return o;
}
__device__ __forceinline__ TSC shfl_up_tsc(const TSC& v, int off) {
    TSC r;
    r.T  = __shfl_up_sync(0xffffffffu, v.T, off);
    r.S0 = __shfl_up_sync(0xffffffffu, v.S0, off);
    r.S1 = __shfl_up_sync(0xffffffffu, v.S1, off);
    r.S2 = __shfl_up_sync(0xffffffffu, v.S2, off);
    r.C0 = __shfl_up_sync(0xffffffffu, v.C0, off);
    r.C1 = __shfl_up_sync(0xffffffffu, v.C1, off);
    r.C2 = __shfl_up_sync(0xffffffffu, v.C2, off);
    return r;
}

// helper: per-row tail (corrections -> out, cacc, delta quat)
__device__ __forceinline__ float4 row_tail(
    int r, float c0, float c1, float c2, float c3, float c4, float c5,
    float x0, float x1, float x2, float x3, float x4, float x5,
    const float* __restrict__ dt, float* __restrict__ out)
{
    size_t ob = (size_t)r * 16;
    out[ob+10] = c0; out[ob+11] = c1; out[ob+12] = c2;
    out[ob+13] = c3; out[ob+14] = c4; out[ob+15] = c5;
    g_cacc[r*3+0] = c0 + x0;
    g_cacc[r*3+1] = c1 + x1;
    g_cacc[r*3+2] = c2 + x2;
    float dtv = dt[r];
    float v0 = (c3 + x3) * dtv;
    float v1 = (c4 + x4) * dtv;
    float v2 = (c5 + x5) * dtv;
    float tt2 = v0*v0 + v1*v1 + v2*v2;
    float theta = sqrtf(tt2 + 1e-16f);
    float half  = 0.5f * theta;
    float w  = cosf(half);
    float sc = (tt2 < 1e-12f) ? (0.5f - tt2 * (1.0f/48.0f)) : (sinf(half) / theta);
    return make_float4(w, v0*sc, v1*sc, v2*sc);
}

// ---------------------------------------------------------------------------
// K1: MLP, 2 rows/thread (weights LDS amortized), dual chunk quat scans,
//     last-block cross-chunk quat scan.
// grid = 256 blocks of 256 threads; block handles chunks 2b, 2b+1
// ---------------------------------------------------------------------------
__global__ void __launch_bounds__(256)
mlp_kernel(const float* __restrict__ acc, const float* __restrict__ gyro,
           const float* __restrict__ dt, const float* __restrict__ init_rot,
           const float* __restrict__ W_enc, const float* __restrict__ b_enc,
           const float* __restrict__ W_dec, const float* __restrict__ b_dec,
           float* __restrict__ out)
{
    __shared__ __align__(16) u64 s_w[128*16];
    __shared__ __align__(16) float4 s_wq[16];   // warp quat totals (A:0-7, B:8-15)
    __shared__ bool s_last;
    int tid = threadIdx.x;
    int lane = tid & 31, wid = tid >> 5;

    if (tid < 128) {
        int p = tid;
        #pragma unroll
        for (int k = 0; k < 6; k++) {
            const float2 v = reinterpret_cast<const float2*>(W_enc + k*HH)[p];
            s_w[p*16 + k] = pk2(v.x, v.y);
        }
        const float2 bb = reinterpret_cast<const float2*>(b_enc)[p];
        s_w[p*16 + 6] = pk2(bb.x, bb.y);
        #pragma unroll
        for (int k = 0; k < 6; k++) {
            s_w[p*16 + 7 + k] = pk2(W_dec[(2*p)*6 + k], W_dec[(2*p+1)*6 + k]);
        }
        s_w[p*16 + 13] = 0; s_w[p*16 + 14] = 0; s_w[p*16 + 15] = 0;
    }
    __syncthreads();

    int rA = blockIdx.x * 512 + tid;      // chunk 2b
    int rB = rA + 256;                    // chunk 2b+1
    float xA0 = acc[rA*3+0], xA1 = acc[rA*3+1], xA2 = acc[rA*3+2];
    float xA3 = gyro[rA*3+0], xA4 = gyro[rA*3+1], xA5 = gyro[rA*3+2];
    float xB0 = acc[rB*3+0], xB1 = acc[rB*3+1], xB2 = acc[rB*3+2];
    float xB3 = gyro[rB*3+0], xB4 = gyro[rB*3+1], xB5 = gyro[rB*3+2];
    u64 XA0 = pk2(xA0,xA0), XA1 = pk2(xA1,xA1), XA2 = pk2(xA2,xA2);
    u64 XA3 = pk2(xA3,xA3), XA4 = pk2(xA4,xA4), XA5 = pk2(xA5,xA5);
    u64 XB0 = pk2(xB0,xB0), XB1 = pk2(xB1,xB1), XB2 = pk2(xB2,xB2);
    u64 XB3 = pk2(xB3,xB3), XB4 = pk2(xB4,xB4), XB5 = pk2(xB5,xB5);

    u64 CU1 = pk2(0.7978845608028654f, 0.7978845608028654f);
    u64 CU3 = pk2(0.035677408136300125f, 0.035677408136300125f);
    u64 HLF = pk2(0.5f, 0.5f);

    u64 aA0=0,aA1=0,aA2=0,aA3=0,aA4=0,aA5=0;
    u64 aB0=0,aB1=0,aB2=0,aB3=0,aB4=0,aB5=0;

    #pragma unroll 2
    for (int p = 0; p < 128; p++) {
        const ulonglong2* q = reinterpret_cast<const ulonglong2*>(s_w + p*16);
        ulonglong2 q0 = q[0], q1 = q[1], q2 = q[2], q3 = q[3], q4 = q[4], q5 = q[5];
        u64 dec5 = reinterpret_cast<const u64*>(s_w + p*16)[12];

        u64 preA = q3.x, preB = q3.x;
        preA = ffma2(q0.x, XA0, preA);  preB = ffma2(q0.x, XB0, preB);
        preA = ffma2(q0.y, XA1, preA);  preB = ffma2(q0.y, XB1, preB);
        preA = ffma2(q1.x, XA2, preA);  preB = ffma2(q1.x, XB2, preB);
        preA = ffma2(q1.y, XA3, preA);  preB = ffma2(q1.y, XB3, preB);
        preA = ffma2(q2.x, XA4, preA);  preB = ffma2(q2.x, XB4, preB);
        preA = ffma2(q2.y, XA5, preA);  preB = ffma2(q2.y, XB5, preB);

        u64 s2A = fmul2(preA, preA);    u64 s2B = fmul2(preB, preB);
        u64 t2A = ffma2(s2A, CU3, CU1); u64 t2B = ffma2(s2B, CU3, CU1);
        u64 upA = fmul2(preA, t2A);     u64 upB = fmul2(preB, t2B);
        float uA0, uA1, uB0, uB1;
        upk2(upA, uA0, uA1); upk2(upB, uB0, uB1);
        u64 thA = pk2(tanha(uA0), tanha(uA1));
        u64 thB = pk2(tanha(uB0), tanha(uB1));
        u64 omA = ffma2(thA, HLF, HLF); u64 omB = ffma2(thB, HLF, HLF);
        u64 ftA = fmul2(preA, omA);     u64 ftB = fmul2(preB, omB);

        aA0 = ffma2(ftA, q3.y, aA0);    aB0 = ffma2(ftB, q3.y, aB0);
        aA1 = ffma2(ftA, q4.x, aA1);    aB1 = ffma2(ftB, q4.x, aB1);
        aA2 = ffma2(ftA, q4.y, aA2);    aB2 = ffma2(ftB, q4.y, aB2);
        aA3 = ffma2(ftA, q5.x, aA3);    aB3 = ffma2(ftB, q5.x, aB3);
        aA4 = ffma2(ftA, q5.y, aA4);    aB4 = ffma2(ftB, q5.y, aB4);
        aA5 = ffma2(ftA, dec5, aA5);    aB5 = ffma2(ftB, dec5, aB5);
    }

    float bd0 = __ldg(&b_dec[0]), bd1 = __ldg(&b_dec[1]), bd2 = __ldg(&b_dec[2]);
    float bd3 = __ldg(&b_dec[3]), bd4 = __ldg(&b_dec[4]), bd5 = __ldg(&b_dec[5]);
    float lo, hi;
    float cA0, cA1, cA2, cA3, cA4, cA5, cB0, cB1, cB2, cB3, cB4, cB5;
    upk2(aA0, lo, hi); cA0 = lo + hi + bd0;
    upk2(aA1, lo, hi); cA1 = lo + hi + bd1;
    upk2(aA2, lo, hi); cA2 = lo + hi + bd2;
    upk2(aA3, lo, hi); cA3 = lo + hi + bd3;
    upk2(aA4, lo, hi); cA4 = lo + hi + bd4;
    upk2(aA5, lo, hi); cA5 = lo + hi + bd5;
    upk2(aB0, lo, hi); cB0 = lo + hi + bd0;
    upk2(aB1, lo, hi); cB1 = lo + hi + bd1;
    upk2(aB2, lo, hi); cB2 = lo + hi + bd2;
    upk2(aB3, lo, hi); cB3 = lo + hi + bd3;
    upk2(aB4, lo, hi); cB4 = lo + hi + bd4;
    upk2(aB5, lo, hi); cB5 = lo + hi + bd5;

    float4 vA = row_tail(rA, cA0,cA1,cA2,cA3,cA4,cA5, xA0,xA1,xA2,xA3,xA4,xA5, dt, out);
    float4 vB = row_tail(rB, cB0,cB1,cB2,cB3,cB4,cB5, xB0,xB1,xB2,xB3,xB4,xB5, dt, out);

    // dual within-chunk inclusive quat scans (independent)
    #pragma unroll
    for (int off = 1; off < 32; off <<= 1) {
        float4 uA = shfl_up_q(vA, off);
        float4 uB = shfl_up_q(vB, off);
        if (lane >= off) { vA = qmul(uA, vA); vB = qmul(uB, vB); }
    }
    if (lane == 31) { s_wq[wid] = vA; s_wq[8 + wid] = vB; }
    __syncthreads();
    float4 wpA = make_float4(1.f, 0.f, 0.f, 0.f);
    float4 wpB = make_float4(1.f, 0.f, 0.f, 0.f);
    for (int wI = 0; wI < wid; wI++) {
        wpA = qmul(wpA, s_wq[wI]);
        wpB = qmul(wpB, s_wq[8 + wI]);
    }
    float4 inclA = qmul(wpA, vA);
    float4 inclB = qmul(wpB, vB);
    g_pq[rA] = inclA;
    g_pq[rB] = inclB;
    if (tid == 255) {
        g_cq[blockIdx.x*2]     = inclA;
        g_cq[blockIdx.x*2 + 1] = inclB;
    }

    // ---- last-block: cross-chunk exclusive quat prefix for all batches ----
    __threadfence();
    __syncthreads();
    if (tid == 0) s_last = (atomicAdd(&g_ctr1, 1u) == gridDim.x - 1);
    __syncthreads();
    if (s_last) {
        __threadfence();
        int b = wid;                 // 8 warps == 8 batches
        float4 d0 = g_cq[b*NCHB + 2*lane];
        float4 d1 = g_cq[b*NCHB + 2*lane + 1];
        float4 pr = qmul(d0, d1);
        #pragma unroll
        for (int off = 1; off < 32; off <<= 1) {
            float4 u = shfl_up_q(pr, off);
            if (lane >= off) pr = qmul(u, pr);
        }
        float4 ex = shfl_up_q(pr, 1);
        float4 q0 = make_float4(init_rot[b*4+0], init_rot[b*4+1],
                                init_rot[b*4+2], init_rot[b*4+3]);
        float4 pre0 = (lane == 0) ? q0 : qmul(q0, ex);
        float4 pre1 = qmul(pre0, d0);
        g_cpre[b*NCHB + 2*lane]     = pre0;
        g_cpre[b*NCHB + 2*lane + 1] = pre1;
        __syncthreads();
        if (tid == 0) g_ctr1 = 0;
    }
}

// ---------------------------------------------------------------------------
// K2: world accel + rot out + within-chunk TSC scan + last-block chunk scan
// grid = 512, block = 256
// ---------------------------------------------------------------------------
__global__ void __launch_bounds__(256)
accel_kernel(const float* __restrict__ dt,
             const float* __restrict__ init_pos, const float* __restrict__ init_vel,
             float* __restrict__ out)
{
    __shared__ TSC s_wt[8];
    __shared__ bool s_last;
    int c = blockIdx.x, j = threadIdx.x;
    int lane = j & 31, wid = j >> 5;
    int e = c*256 + j;

    float4 cpre = g_cpre[c];
    float4 myq = g_pq[e];
    float4 Ee = (j == 0) ? cpre : qmul(cpre, g_pq[e-1]);
    float rn = rsqrtf(Ee.x*Ee.x + Ee.y*Ee.y + Ee.z*Ee.z + Ee.w*Ee.w);
    float qw = Ee.x*rn, q1 = Ee.y*rn, q2 = Ee.z*rn, q3 = Ee.w*rn;

    float v1 = g_cacc[e*3+0], v2 = g_cacc[e*3+1], v3 = g_cacc[e*3+2];
    float t1 = (q2*v3 - q3*v2) + qw*v1;
    float t2 = (q3*v1 - q1*v3) + qw*v2;
    float t3 = (q1*v2 - q2*v1) + qw*v3;
    float a0 = v1 + 2.0f*(q2*t3 - q3*t2);
    float a1 = v2 + 2.0f*(q3*t1 - q1*t3);
    float a2 = v3 + 2.0f*(q1*t2 - q2*t1) - 9.81007f;

    float4 Ei = qmul(cpre, myq);
    float rn2 = rsqrtf(Ei.x*Ei.x + Ei.y*Ei.y + Ei.z*Ei.z + Ei.w*Ei.w);
    size_t ob = (size_t)e * 16;
    out[ob+6] = Ei.x*rn2; out[ob+7] = Ei.y*rn2;
    out[ob+8] = Ei.z*rn2; out[ob+9] = Ei.w*rn2;

    float dtv = dt[e];
    float hd = 0.5f*dtv*dtv;
    TSC v; v.T = dtv;
    v.S0 = a0*dtv; v.S1 = a1*dtv; v.S2 = a2*dtv;
    v.C0 = a0*hd;  v.C1 = a1*hd;  v.C2 = a2*hd;

    #pragma unroll
    for (int off = 1; off < 32; off <<= 1) {
        TSC u = shfl_up_tsc(v, off);
        if (lane >= off) v = tsc_comb(u, v);
    }
    if (lane == 31) s_wt[wid] = v;
    __syncthreads();
    TSC wp; wp.T=0.f; wp.S0=0.f; wp.S1=0.f; wp.S2=0.f; wp.C0=0.f; wp.C1=0.f; wp.C2=0.f;
    for (int wI = 0; wI < wid; wI++) wp = tsc_comb(wp, s_wt[wI]);
    TSC incl = tsc_comb(wp, v);

    g_eTSC[0*(size_t)NROWS + e] = incl.T;
    g_eTSC[1*(size_t)NROWS + e] = incl.S0;
    g_eTSC[2*(size_t)NROWS + e] = incl.S1;
    g_eTSC[3*(size_t)NROWS + e] = incl.S2;
    g_eTSC[4*(size_t)NROWS + e] = incl.C0;
    g_eTSC[5*(size_t)NROWS + e] = incl.C1;
    g_eTSC[6*(size_t)NROWS + e] = incl.C2;
    if (j == 255) {
        g_cTSC[c*7+0]=incl.T;
        g_cTSC[c*7+1]=incl.S0; g_cTSC[c*7+2]=incl.S1; g_cTSC[c*7+3]=incl.S2;
        g_cTSC[c*7+4]=incl.C0; g_cTSC[c*7+5]=incl.C1; g_cTSC[c*7+6]=incl.C2;
    }

    __threadfence();
    __syncthreads();
    if (j == 0) s_last = (atomicAdd(&g_ctr2, 1u) == gridDim.x - 1);
    __syncthreads();
    if (s_last) {
        __threadfence();
        int b = wid;
        int c0i = b*NCHB + 2*lane, c1i = c0i + 1;
        TSC d0, d1;
        d0.T=g_cTSC[c0i*7+0]; d0.S0=g_cTSC[c0i*7+1]; d0.S1=g_cTSC[c0i*7+2]; d0.S2=g_cTSC[c0i*7+3];
        d0.C0=g_cTSC[c0i*7+4]; d0.C1=g_cTSC[c0i*7+5]; d0.C2=g_cTSC[c0i*7+6];
        d1.T=g_cTSC[c1i*7+0]; d1.S0=g_cTSC[c1i*7+1]; d1.S1=g_cTSC[c1i*7+2]; d1.S2=g_cTSC[c1i*7+3];
        d1.C0=g_cTSC[c1i*7+4]; d1.C1=g_cTSC[c1i*7+5]; d1.C2=g_cTSC[c1i*7+6];
        TSC pr = tsc_comb(d0, d1);
        #pragma unroll
        for (int off = 1; off < 32; off <<= 1) {
            TSC u = shfl_up_tsc(pr, off);
            if (lane >= off) pr = tsc_comb(u, pr);
        }
        TSC ex = shfl_up_tsc(pr, 1);
        if (lane == 0) { ex.T=0.f; ex.S0=0.f; ex.S1=0.f; ex.S2=0.f; ex.C0=0.f; ex.C1=0.f; ex.C2=0.f; }
        TSC ex1 = tsc_comb(ex, d0);
        float ip0 = init_pos[b*3+0], ip1 = init_pos[b*3+1], ip2 = init_pos[b*3+2];
        float iv0 = init_vel[b*3+0], iv1 = init_vel[b*3+1], iv2 = init_vel[b*3+2];
        g_cstart[c0i*6+0] = ip0 + iv0*ex.T + ex.C0;
        g_cstart[c0i*6+1] = ip1 + iv1*ex.T + ex.C1;
        g_cstart[c0i*6+2] = ip2 + iv2*ex.T + ex.C2;
        g_cstart[c0i*6+3] = iv0 + ex.S0;
        g_cstart[c0i*6+4] = iv1 + ex.S1;
        g_cstart[c0i*6+5] = iv2 + ex.S2;
        g_cstart[c1i*6+0] = ip0 + iv0*ex1.T + ex1.C0;
        g_cstart[c1i*6+1] = ip1 + iv1*ex1.T + ex1.C1;
        g_cstart[c1i*6+2] = ip2 + iv2*ex1.T + ex1.C2;
        g_cstart[c1i*6+3] = iv0 + ex1.S0;
        g_cstart[c1i*6+4] = iv1 + ex1.S1;
        g_cstart[c1i*6+5] = iv2 + ex1.S2;
        __syncthreads();
        if (j == 0) g_ctr2 = 0;
    }
}

// ---------------------------------------------------------------------------
// K3: final per-element pos/vel
// ---------------------------------------------------------------------------
__global__ void __launch_bounds__(256)
posvel_kernel(float* __restrict__ out)
{
    int c = blockIdx.x, j = threadIdx.x;
    int e = c*256 + j;
    float ps0 = g_cstart[c*6+0], ps1 = g_cstart[c*6+1], ps2 = g_cstart[c*6+2];
    float vs0 = g_cstart[c*6+3], vs1 = g_cstart[c*6+4], vs2 = g_cstart[c*6+5];
    float T  = g_eTSC[0*(size_t)NROWS + e];
    float S0 = g_eTSC[1*(size_t)NROWS + e];
    float S1 = g_eTSC[2*(size_t)NROWS + e];
    float S2 = g_eTSC[3*(size_t)NROWS + e];
    float C0 = g_eTSC[4*(size_t)NROWS + e];
    float C1 = g_eTSC[5*(size_t)NROWS + e];
    float C2 = g_eTSC[6*(size_t)NROWS + e];
    size_t ob = (size_t)e * 16;
    out[ob+0] = ps0 + vs0*T + C0;
    out[ob+1] = ps1 + vs1*T + C1;
    out[ob+2] = ps2 + vs2*T + C2;
    out[ob+3] = vs0 + S0;
    out[ob+4] = vs1 + S1;
    out[ob+5] = vs2 + S2;
}

// ---------------------------------------------------------------------------
extern "C" void kernel_launch(void* const* d_in, const int* in_sizes, int n_in,
                              void* d_out, int out_size)
{
    const float* acc      = (const float*)d_in[0];
    const float* gyro     = (const float*)d_in[1];
    const float* dt       = (const float*)d_in[2];
    const float* init_pos = (const float*)d_in[3];
    const float* init_vel = (const float*)d_in[4];
    const float* init_rot = (const float*)d_in[5];
    const float* W_enc    = (const float*)d_in[6];
    const float* b_enc    = (const float*)d_in[7];
    const float* W_dec    = (const float*)d_in[8];
    const float* b_dec    = (const float*)d_in[9];
    float* out = (float*)d_out;

    mlp_kernel<<<NCHT/2, 256>>>(acc, gyro, dt, init_rot, W_enc, b_enc, W_dec, b_dec, out);
    accel_kernel<<<NCHT, 256>>>(dt, init_pos, init_vel, out);
    posvel_kernel<<<NCHT, 256>>>(out);
}